// round 10
// baseline (speedup 1.0000x reference)
#include <cuda_runtime.h>
#include <stdint.h>

// GraphRewiring: transitive closure of body-edge adjacency (attr==0),
// emit shortcut edges (closure & ~adj) appended to original edge list.
//
// R10: ZERO software barriers. 4 kernels; CUDA-graph edges provide all
// ordering (R8/R9 evidence: graph-node boundaries cost ~ the same as a
// software grid barrier, without skew or co-residency constraints).
//
//   K1 init : zero adj/radj, pivot=0, detect int64-vs-int32
//   K2 build: copy originals, scatter adj/radj bitsets, pivot=max body dst
//   K3 bfsp : blocks 0,1 = fwd/bwd BFS from pivot -> F, B (32 warps/block);
//             blocks 2.. = prewrite the dense all-shortcut output pattern
//   K4 close: per-warp LOCAL closure via BFS over the static seed matrix
//               S[k] = adj[k] | (k in B ? F u {p} : 0)
//             (no inter-row sync needed: S is stable), then each warp emits
//             its own row's fix-up words (only where sc != 0xFFFFFFFF).
//
// Why BFS over S = true closure:
//   (<=) S[k] \subseteq closure(k):  adj[k] trivially; k in B => k reaches p
//        => closure(k) \supseteq {p} u closure(p) = {p} u F.
//   (>=) S \supseteq adj pointwise => BFS over S \supseteq BFS over adj.
//   Absorption: k in F&B => closure(k) = F exactly (p reaches k => closure(k)
//   \subseteq F; k reaches p => closure(k) \supseteq F; and F&B nonempty =>
//   p on a cycle => p in F). So delta bits in F&B contribute F with NO load.
//   k in F (even \B) => adj[k] \subseteq closure(k) \subseteq F.
//
// Output layout (float32, out_size = 3*(E+N*N)):
//   [0, E)               : edge_index[0] (src) as float
//   [E, E+NN)            : new_src
//   [E+NN, 2E+NN)        : edge_index[1] (dst) as float
//   [2E+NN, 2E+2NN)      : new_dst
//   [2(E+NN), 2(E+NN)+E) : edge_attr copy
//   [2(E+NN)+E, 3(E+NN)) : new_attr (3.0 if shortcut else -1.0)

#define N_NODES 1024
#define NW 32
#define FULLMASK 0xFFFFFFFFu

static __device__ uint32_t g_adj[N_NODES * NW];
static __device__ uint32_t g_radj[N_NODES * NW];
static __device__ uint32_t g_F[NW];
static __device__ uint32_t g_B[NW];
static __device__ int g_pivot;
static __device__ int g_i64flag;

// ---------------------------------------------------------------------------
// K1: zero adjacency scratch + pivot, detect dtype. Graph edge orders this
// before K2 (free barrier).
__global__ void init_kernel(const int* __restrict__ ei32) {
    int t = blockIdx.x * blockDim.x + threadIdx.x;   // 0..32767
    g_adj[t] = 0u;
    g_radj[t] = 0u;
    if (t == 0) {
        g_pivot = 0;
        // int64 little-endian with node ids < 1024 => every odd word is 0.
        int allzero = 1;
        for (int k = 0; k < 64; k++)
            if (ei32[2 * k + 1] != 0) { allzero = 0; break; }
        g_i64flag = allzero;
    }
}

// ---------------------------------------------------------------------------
// K2: copy originals + scatter adj/radj + pivot (max body dst, deterministic).
__global__ void build_kernel(const int* __restrict__ ei32,
                             const float* __restrict__ attr,
                             float* __restrict__ out, int E) {
    const int NN = N_NODES * N_NODES;
    int e = blockIdx.x * blockDim.x + threadIdx.x;
    int lane = threadIdx.x & 31;
    bool v = (e < E);
    int src = 0, dst = 0; float a = 1.0f;
    if (v) {
        if (g_i64flag) { src = ei32[2 * e]; dst = ei32[2 * (E + e)]; }
        else           { src = ei32[e];     dst = ei32[E + e]; }
        a = attr[e];
        out[e] = (float)src;
        out[(E + NN) + e] = (float)dst;
        out[2 * (E + NN) + e] = a;
    }
    bool body = v && (a == 0.0f);
    if (body) {
        atomicOr(&g_adj[src * NW + (dst >> 5)], 1u << (dst & 31));
        atomicOr(&g_radj[dst * NW + (src >> 5)], 1u << (src & 31));
    }
    int m = __reduce_max_sync(FULLMASK, body ? dst : -1);
    if (lane == 0 && m >= 0) atomicMax(&g_pivot, m);
}

// ---------------------------------------------------------------------------
// Emit one 32-slot output word across all three segments. Prewrite uses
// sc=FULLMASK; fix-up recomputes the identical formula.
__device__ __forceinline__ void emit_word(float* __restrict__ out, int E,
                                          int w, uint32_t sc) {
    const int NN = N_NODES * N_NODES;
    int p_base = w << 5;
    int j0 = (w & 31) << 5;
    float fi = (float)(w >> 5);

    float* so = out + E + p_base;                   // new_src
    float* dd = out + (E + NN) + E + p_base;        // new_dst
    float* ao = out + 2 * (E + NN) + E + p_base;    // new_attr

    #pragma unroll
    for (int q = 0; q < 32; q += 4) {
        bool b0 = (sc >> (q + 0)) & 1u;
        bool b1 = (sc >> (q + 1)) & 1u;
        bool b2 = (sc >> (q + 2)) & 1u;
        bool b3 = (sc >> (q + 3)) & 1u;
        float4 s4 = make_float4(b0 ? fi : 0.f, b1 ? fi : 0.f,
                                b2 ? fi : 0.f, b3 ? fi : 0.f);
        float4 d4 = make_float4(b0 ? (float)(j0 + q + 0) : 0.f,
                                b1 ? (float)(j0 + q + 1) : 0.f,
                                b2 ? (float)(j0 + q + 2) : 0.f,
                                b3 ? (float)(j0 + q + 3) : 0.f);
        float4 a4 = make_float4(b0 ? 3.f : -1.f, b1 ? 3.f : -1.f,
                                b2 ? 3.f : -1.f, b3 ? 3.f : -1.f);
        *(float4*)(so + q) = s4;
        *(float4*)(dd + q) = d4;
        *(float4*)(ao + q) = a4;
    }
}

// ---------------------------------------------------------------------------
// K3: blocks 0,1 = single-source BFS to fixpoint (32 warps, 1 word each);
//     blocks 2.. = prewrite dense output pattern (runs concurrently).
__global__ void __launch_bounds__(1024, 1)
bfs_prewrite_kernel(float* __restrict__ out, int E) {
    __shared__ uint32_t sR[NW], sExp[NW], sFr[NW];
    __shared__ int sAny;
    const int lane = threadIdx.x & 31;
    const int wid  = threadIdx.x >> 5;               // 0..31

    if (blockIdx.x <= 1) {
        const uint32_t* Adj = (blockIdx.x == 0) ? g_adj : g_radj;
        const int p = g_pivot;
        if (threadIdx.x < NW) { sR[threadIdx.x] = Adj[p * NW + threadIdx.x];
                                sExp[threadIdx.x] = 0u; }
        __syncthreads();
        for (int level = 0; level < N_NODES + 1; level++) {
            if (threadIdx.x == 0) sAny = 0;
            __syncthreads();
            if (threadIdx.x < NW) {
                sFr[threadIdx.x] = sR[threadIdx.x] & ~sExp[threadIdx.x];
                sExp[threadIdx.x] = sR[threadIdx.x];
                if (sFr[threadIdx.x]) sAny = 1;      // benign race, all write 1
            }
            __syncthreads();
            if (!sAny) break;
            // warp 'wid' expands frontier word 'wid' (1 word per warp).
            uint32_t bits = sFr[wid];                // warp-uniform
            uint32_t accum = 0;
            const uint32_t* pk = &Adj[(wid << 10) + lane];
            while (bits) {
                int j0 = __ffs(bits) - 1; bits &= bits - 1;
                int j1 = j0, j2 = j0, j3 = j0;
                int j4 = j0, j5 = j0, j6 = j0, j7 = j0;
                if (bits) { j1 = __ffs(bits) - 1; bits &= bits - 1; }
                if (bits) { j2 = __ffs(bits) - 1; bits &= bits - 1; }
                if (bits) { j3 = __ffs(bits) - 1; bits &= bits - 1; }
                if (bits) { j4 = __ffs(bits) - 1; bits &= bits - 1; }
                if (bits) { j5 = __ffs(bits) - 1; bits &= bits - 1; }
                if (bits) { j6 = __ffs(bits) - 1; bits &= bits - 1; }
                if (bits) { j7 = __ffs(bits) - 1; bits &= bits - 1; }
                uint32_t v0 = pk[j0 << 5];
                uint32_t v1 = pk[j1 << 5];
                uint32_t v2 = pk[j2 << 5];
                uint32_t v3 = pk[j3 << 5];
                uint32_t v4 = pk[j4 << 5];
                uint32_t v5 = pk[j5 << 5];
                uint32_t v6 = pk[j6 << 5];
                uint32_t v7 = pk[j7 << 5];
                accum |= (v0 | v1) | (v2 | v3) | (v4 | v5) | (v6 | v7);
            }
            if (accum) atomicOr(&sR[lane], accum);
            __syncthreads();
        }
        if (threadIdx.x < NW) {
            if (blockIdx.x == 0) g_F[threadIdx.x] = sR[threadIdx.x];
            else                 g_B[threadIdx.x] = sR[threadIdx.x];
        }
    } else {
        // Prewrite dense "all shortcut" pattern for every output word.
        int t = (blockIdx.x - 2) * 1024 + threadIdx.x;
        for (int w = t; w < N_NODES * NW; w += (gridDim.x - 2) * 1024)
            emit_word(out, E, w, FULLMASK);
    }
}

// ---------------------------------------------------------------------------
// K4: warp-local closure over the static seed matrix S, then emit fix-up.
// 64 blocks x 512 threads = 1024 warps, warp == row. No inter-warp sync.
__global__ void __launch_bounds__(512)
closure_emit_kernel(float* __restrict__ out, int E) {
    const int tid  = blockIdx.x * 512 + threadIdx.x;
    const int lane = threadIdx.x & 31;
    const int row  = tid >> 5;                       // 0..1023

    const uint32_t Fl = g_F[lane];                   // lane-resident F bitset
    const uint32_t Bl = g_B[lane];                   // lane-resident B bitset
    const int p = g_pivot;
    const uint32_t pbit = (lane == (p >> 5)) ? (1u << (p & 31)) : 0u;
    const uint32_t FBl = Fl & Bl;

    const uint32_t adjrow = g_adj[(row << 5) + lane];
    const int inB = (__shfl_sync(FULLMASK, Bl, row >> 5) >> (row & 31)) & 1;

    uint32_t acc = adjrow | (inB ? (Fl | pbit) : 0u);
    uint32_t expanded = inB ? FBl : 0u;  // F&B absorbed: closure(k)=F \subseteq acc

    // Local BFS over S until fixpoint (typically 1-3 tiny rounds).
    while (true) {
        uint32_t delta = acc & ~expanded;
        if (!__any_sync(FULLMASK, delta != 0u)) break;
        expanded = acc;
        uint32_t add = 0;
        #pragma unroll 1
        for (int kw = 0; kw < NW; kw++) {
            uint32_t bits = __shfl_sync(FULLMASK, delta, kw);  // warp-uniform
            if (!bits) continue;
            uint32_t FBw = __shfl_sync(FULLMASK, FBl, kw);
            uint32_t Bw  = __shfl_sync(FULLMASK, Bl, kw);
            if (bits & FBw) add |= Fl;            // k in F&B: closure(k)=F, no load
            uint32_t rest = bits & ~FBw;          // must load adj[k]
            if (rest & Bw) add |= Fl | pbit;      // k in B\F: + analytic F u {p}
            const uint32_t* pk = &g_adj[(kw << 10) + lane];
            while (rest) {
                int j0 = __ffs(rest) - 1; rest &= rest - 1;
                int j1 = j0, j2 = j0, j3 = j0;
                if (rest) { j1 = __ffs(rest) - 1; rest &= rest - 1; }
                if (rest) { j2 = __ffs(rest) - 1; rest &= rest - 1; }
                if (rest) { j3 = __ffs(rest) - 1; rest &= rest - 1; }
                add |= pk[j0 << 5] | pk[j1 << 5] | pk[j2 << 5] | pk[j3 << 5];
            }
        }
        uint32_t na = acc | add;
        if (__all_sync(FULLMASK, na == acc)) break;
        acc = na;
    }

    // Emit this lane's output word (fix-up only where it differs from the
    // prewritten all-shortcut pattern).
    uint32_t sc = acc & ~adjrow;
    if (sc != FULLMASK)
        emit_word(out, E, (row << 5) + lane, sc);
}

// ---------------------------------------------------------------------------
extern "C" void kernel_launch(void* const* d_in, const int* in_sizes, int n_in,
                              void* d_out, int out_size) {
    const int* ei = (const int*)d_in[0];
    const float* attr = (const float*)d_in[1];
    float* out = (float*)d_out;
    int E = in_sizes[1];

    init_kernel<<<64, 512>>>(ei);
    build_kernel<<<(E + 511) / 512, 512>>>(ei, attr, out, E);
    bfs_prewrite_kernel<<<64, 1024>>>(out, E);
    closure_emit_kernel<<<64, 512>>>(out, E);
}

// round 11
// speedup vs baseline: 1.0678x; 1.0678x over previous
#include <cuda_runtime.h>
#include <stdint.h>

// GraphRewiring: transitive closure of body-edge adjacency (attr==0),
// emit shortcut edges (closure & ~adj) appended to original edge list.
//
// R11: R9 skeleton (2 launches + pure-poll barriers, measured best) with the
// expansion phase replaced by a CLOSED-FORM closure (no kw-sweep, no extra
// barriers):
//   closure(row) = adjrow u U_{k in adjrow} closure(k), absorbed by:
//     (a) k in F&B  => closure(k) = F           (zero loads; p in F)
//     (b) k in B    => closure(k) >= F u {p}    (one ballot, analytic)
//     (c) F in acc  => any k in F absorbed      (closure(k) <= F for k in F)
//   => per round only bits in (delta & ~F) need adj loads (~0-2 nodes here).
//
//   launch 1: init (zero adj/radj, barrier slots, pivot; dtype detect)
//   launch 2: fused, GRID=64 x TPB=512 (1 block/SM, co-resident):
//     P1  build: copy originals, scatter adj/radj, pivot=max body dst   [bar]
//     P2  blocks 0,1: fwd/bwd BFS from pivot -> F, B
//         blocks 2..: prewrite dense all-shortcut output pattern        [bar]
//     P3' per-warp closed-form closure + fix-up emit (no sync at all)
//
// Output layout (float32, out_size = 3*(E+N*N)):
//   [0, E)               : edge_index[0] (src) as float
//   [E, E+NN)            : new_src
//   [E+NN, 2E+NN)        : edge_index[1] (dst) as float
//   [2E+NN, 2E+2NN)      : new_dst
//   [2(E+NN), 2(E+NN)+E) : edge_attr copy
//   [2(E+NN)+E, 3(E+NN)) : new_attr (3.0 if shortcut else -1.0)

#define N_NODES 1024
#define NW 32
#define FULLMASK 0xFFFFFFFFu
#define GRID 64
#define TPB 512
#define NBAR 4

static __device__ uint32_t g_adj[N_NODES * NW];
static __device__ uint32_t g_radj[N_NODES * NW];
static __device__ uint32_t g_F[NW];
static __device__ uint32_t g_B[NW];
static __device__ int g_pivot;
static __device__ int g_i64flag;
static __device__ int g_bar[NBAR];

// ---------------------------------------------------------------------------
// init: zero scratch + per-replay barrier slots, detect dtype.
__global__ void init_kernel(const int* __restrict__ ei32) {
    int t = blockIdx.x * blockDim.x + threadIdx.x;   // 0..32767
    g_adj[t] = 0u;
    g_radj[t] = 0u;
    if (t < NBAR) g_bar[t] = 0;
    if (t == 0) {
        g_pivot = 0;
        // int64 little-endian with node ids < 1024 => every odd word is 0.
        int allzero = 1;
        for (int k = 0; k < 64; k++)
            if (ei32[2 * k + 1] != 0) { allzero = 0; break; }
        g_i64flag = allzero;
    }
}

// ---------------------------------------------------------------------------
// Pure-poll grid barrier. 64 blocks x 512 threads at 1 block/SM => all
// co-resident, spin deadlock-free. Release fence before arrive; acquire
// fence after spin.
__device__ __forceinline__ void grid_sync(int slot) {
    __syncthreads();
    if (threadIdx.x == 0) {
        __threadfence();
        atomicAdd(&g_bar[slot], 1);
        while (*(volatile int*)&g_bar[slot] < GRID) { }
        __threadfence();
    }
    __syncthreads();
}

// ---------------------------------------------------------------------------
// Emit one 32-slot output word across all three segments. Prewrite uses
// sc=FULLMASK; fix-up recomputes the identical formula.
__device__ __forceinline__ void emit_word(float* __restrict__ out, int E,
                                          int w, uint32_t sc) {
    const int NN = N_NODES * N_NODES;
    int p_base = w << 5;
    int j0 = (w & 31) << 5;
    float fi = (float)(w >> 5);

    float* so = out + E + p_base;                   // new_src
    float* dd = out + (E + NN) + E + p_base;        // new_dst
    float* ao = out + 2 * (E + NN) + E + p_base;    // new_attr

    #pragma unroll
    for (int q = 0; q < 32; q += 4) {
        bool b0 = (sc >> (q + 0)) & 1u;
        bool b1 = (sc >> (q + 1)) & 1u;
        bool b2 = (sc >> (q + 2)) & 1u;
        bool b3 = (sc >> (q + 3)) & 1u;
        float4 s4 = make_float4(b0 ? fi : 0.f, b1 ? fi : 0.f,
                                b2 ? fi : 0.f, b3 ? fi : 0.f);
        float4 d4 = make_float4(b0 ? (float)(j0 + q + 0) : 0.f,
                                b1 ? (float)(j0 + q + 1) : 0.f,
                                b2 ? (float)(j0 + q + 2) : 0.f,
                                b3 ? (float)(j0 + q + 3) : 0.f);
        float4 a4 = make_float4(b0 ? 3.f : -1.f, b1 ? 3.f : -1.f,
                                b2 ? 3.f : -1.f, b3 ? 3.f : -1.f);
        *(float4*)(so + q) = s4;
        *(float4*)(dd + q) = d4;
        *(float4*)(ao + q) = a4;
    }
}

// ---------------------------------------------------------------------------
__global__ void __launch_bounds__(TPB, 1)
fused_kernel(const int* __restrict__ ei32, const float* __restrict__ attr,
             float* __restrict__ out, int E) {
    __shared__ uint32_t sR[NW], sExp[NW], sFr[NW];
    __shared__ int sAny;

    const int tid  = blockIdx.x * TPB + threadIdx.x;   // 0..32767
    const int lane = threadIdx.x & 31;
    const int wid  = threadIdx.x >> 5;                 // 0..15
    const int row  = tid >> 5;                         // warp == row, 0..1023
    const int NN   = N_NODES * N_NODES;
    const int i64  = g_i64flag;

    // ---- P1: copy originals + scatter adj/radj + pivot ---------------------
    {
        const int stride = GRID * TPB;                 // 32768
        const int nloops = (E + stride - 1) / stride;
        for (int i = 0; i < nloops; i++) {             // warp-uniform count
            int e = tid + i * stride;
            bool v = (e < E);
            int src = 0, dst = 0; float a = 1.0f;
            if (v) {
                if (i64) { src = ei32[2 * e]; dst = ei32[2 * (E + e)]; }
                else     { src = ei32[e];     dst = ei32[E + e]; }
                a = attr[e];
                out[e] = (float)src;
                out[(E + NN) + e] = (float)dst;
                out[2 * (E + NN) + e] = a;
            }
            bool body = v && (a == 0.0f);
            if (body) {
                atomicOr(&g_adj[src * NW + (dst >> 5)], 1u << (dst & 31));
                atomicOr(&g_radj[dst * NW + (src >> 5)], 1u << (src & 31));
            }
            int m = __reduce_max_sync(FULLMASK, body ? dst : -1);
            if (lane == 0 && m >= 0) atomicMax(&g_pivot, m);
        }
    }
    grid_sync(0);

    // ---- P2: blocks 0,1 = BFS (F fwd / B bwd); blocks 2.. = prewrite -------
    if (blockIdx.x <= 1) {
        const uint32_t* Adj = (blockIdx.x == 0) ? g_adj : g_radj;
        const int p = *(volatile int*)&g_pivot;
        if (threadIdx.x < NW) { sR[threadIdx.x] = Adj[p * NW + threadIdx.x];
                                sExp[threadIdx.x] = 0u; }
        __syncthreads();
        for (int level = 0; level < N_NODES + 1; level++) {
            if (threadIdx.x == 0) sAny = 0;
            __syncthreads();
            if (threadIdx.x < NW) {
                sFr[threadIdx.x] = sR[threadIdx.x] & ~sExp[threadIdx.x];
                sExp[threadIdx.x] = sR[threadIdx.x];
                if (sFr[threadIdx.x]) sAny = 1;        // benign race
            }
            __syncthreads();
            if (!sAny) break;
            uint32_t accum = 0;
            #pragma unroll 1
            for (int ww = wid; ww < NW; ww += 16) {    // 16 warps, 2 words ea.
                uint32_t bits = sFr[ww];               // warp-uniform
                const uint32_t* pk = &Adj[(ww << 10) + lane];
                while (bits) {
                    int j0 = __ffs(bits) - 1; bits &= bits - 1;
                    int j1 = j0, j2 = j0, j3 = j0;
                    int j4 = j0, j5 = j0, j6 = j0, j7 = j0;
                    if (bits) { j1 = __ffs(bits) - 1; bits &= bits - 1; }
                    if (bits) { j2 = __ffs(bits) - 1; bits &= bits - 1; }
                    if (bits) { j3 = __ffs(bits) - 1; bits &= bits - 1; }
                    if (bits) { j4 = __ffs(bits) - 1; bits &= bits - 1; }
                    if (bits) { j5 = __ffs(bits) - 1; bits &= bits - 1; }
                    if (bits) { j6 = __ffs(bits) - 1; bits &= bits - 1; }
                    if (bits) { j7 = __ffs(bits) - 1; bits &= bits - 1; }
                    uint32_t v0 = pk[j0 << 5];
                    uint32_t v1 = pk[j1 << 5];
                    uint32_t v2 = pk[j2 << 5];
                    uint32_t v3 = pk[j3 << 5];
                    uint32_t v4 = pk[j4 << 5];
                    uint32_t v5 = pk[j5 << 5];
                    uint32_t v6 = pk[j6 << 5];
                    uint32_t v7 = pk[j7 << 5];
                    accum |= (v0 | v1) | (v2 | v3) | (v4 | v5) | (v6 | v7);
                }
            }
            if (accum) atomicOr(&sR[lane], accum);
            __syncthreads();
        }
        if (threadIdx.x < NW) {
            if (blockIdx.x == 0) g_F[threadIdx.x] = sR[threadIdx.x];
            else                 g_B[threadIdx.x] = sR[threadIdx.x];
        }
    } else {
        // Prewrite the dense "all shortcut" pattern, hidden in BFS's shadow.
        int t = (blockIdx.x - 2) * TPB + threadIdx.x;
        for (int w = t; w < N_NODES * NW; w += (GRID - 2) * TPB)
            emit_word(out, E, w, FULLMASK);
    }
    grid_sync(1);

    // ---- P3': closed-form closure per warp + fix-up emit (no sync) ---------
    {
        const uint32_t Fl  = __ldcg(&g_F[lane]);       // lane-resident bitsets
        const uint32_t Bl  = __ldcg(&g_B[lane]);
        const uint32_t FBl = Fl & Bl;
        const int p = *(volatile int*)&g_pivot;
        const uint32_t pbit = (lane == (p >> 5)) ? (1u << (p & 31)) : 0u;

        const uint32_t adjrow = g_adj[(row << 5) + lane];
        const int inB = (__shfl_sync(FULLMASK, Bl, row >> 5) >> (row & 31)) & 1;

        uint32_t acc = adjrow;
        bool haveF = false;
        if (inB) { acc |= Fl | pbit; haveF = true; }   // closure(row) >= F u {p}
        uint32_t expanded = 0;

        #pragma unroll 1
        for (int round = 0; round < N_NODES; round++) {
            uint32_t delta = acc & ~expanded;
            if (!__any_sync(FULLMASK, delta != 0u)) break;
            expanded = acc;
            uint32_t add = 0;

            // (b) any delta node in B contributes F u {p} analytically.
            bool hitB = __any_sync(FULLMASK, (delta & Bl) != 0u);
            bool willF = haveF || hitB;
            if (hitB) add |= Fl | pbit;

            // Loads needed only for delta bits not absorbed:
            //   k in F&B        -> closure(k) = F          (never load)
            //   k in F, willF   -> closure(k) <= F         (skip load)
            uint32_t loadbits = delta & ~FBl;
            if (willF) loadbits &= ~Fl;

            uint32_t wordmask = __ballot_sync(FULLMASK, loadbits != 0u);
            while (wordmask) {
                int l = __ffs(wordmask) - 1; wordmask &= wordmask - 1;
                uint32_t bits = __shfl_sync(FULLMASK, loadbits, l);
                const uint32_t* pk = &g_adj[(l << 10) + lane];
                while (bits) {
                    int j0 = __ffs(bits) - 1; bits &= bits - 1;
                    int j1 = j0, j2 = j0, j3 = j0;
                    if (bits) { j1 = __ffs(bits) - 1; bits &= bits - 1; }
                    if (bits) { j2 = __ffs(bits) - 1; bits &= bits - 1; }
                    if (bits) { j3 = __ffs(bits) - 1; bits &= bits - 1; }
                    add |= pk[j0 << 5] | pk[j1 << 5] | pk[j2 << 5] | pk[j3 << 5];
                }
            }

            uint32_t na = acc | add;
            haveF = willF;
            if (__all_sync(FULLMASK, na == acc)) break;
            acc = na;
        }

        // Fix-up emit: lane owns output word row*32+lane.
        uint32_t sc = acc & ~adjrow;
        if (sc != FULLMASK)
            emit_word(out, E, (row << 5) + lane, sc);
    }
}

// ---------------------------------------------------------------------------
extern "C" void kernel_launch(void* const* d_in, const int* in_sizes, int n_in,
                              void* d_out, int out_size) {
    const int* ei = (const int*)d_in[0];
    const float* attr = (const float*)d_in[1];
    float* out = (float*)d_out;
    int E = in_sizes[1];

    init_kernel<<<64, 512>>>(ei);
    fused_kernel<<<GRID, TPB>>>(ei, attr, out, E);
}

// round 12
// speedup vs baseline: 1.1796x; 1.1047x over previous
#include <cuda_runtime.h>
#include <stdint.h>

// GraphRewiring: transitive closure of body-edge adjacency (attr==0),
// emit shortcut edges (closure & ~adj) appended to original edge list.
//
// R12: COALESCED row emit. Diagnosis: every prior emit gave each thread a
// private 128B span, so each STG.128 touched 32 distinct lines = 32 L1tex
// wavefronts (~256x the coalesced cost) => ~8-10us hidden in LSU issue.
// Now the warp owning row r writes the row's contiguous 3x4KB output span
// with lane-interleaved float4 stores (1 wavefront each). Prewrite+fixup
// split deleted (pointless once stores are cheap); P2's idle blocks copy
// the original edges instead.
//
//   launch 1: init (zero adj/radj, barrier slots; dtype detect)
//   launch 2: fused, GRID=64 x TPB=512 (1 block/SM, co-resident):
//     P1  scatter adj/radj bitsets, pivot = max body dst              [bar]
//     P2  blocks 0,1: fwd/bwd BFS from pivot -> F, B
//         blocks 2..: copy original edges to output head              [bar]
//     P3' per-warp closed-form closure + coalesced full-row emit
//
// Closed-form closure (validated R11):
//   closure(row) = adjrow u U_{k in adjrow} closure(k), absorbed by:
//     (a) k in F&B => closure(k) = F        (zero loads; p in F)
//     (b) k in B   => closure(k) >= F u {p} (one ballot, analytic)
//     (c) F already in acc => any k in F absorbed (closure(k) <= F)
//
// Output layout (float32, out_size = 3*(E+N*N)):
//   [0, E)               : edge_index[0] (src) as float
//   [E, E+NN)            : new_src
//   [E+NN, 2E+NN)        : edge_index[1] (dst) as float
//   [2E+NN, 2E+2NN)      : new_dst
//   [2(E+NN), 2(E+NN)+E) : edge_attr copy
//   [2(E+NN)+E, 3(E+NN)) : new_attr (3.0 if shortcut else -1.0)

#define N_NODES 1024
#define NW 32
#define FULLMASK 0xFFFFFFFFu
#define GRID 64
#define TPB 512
#define NBAR 4

static __device__ uint32_t g_adj[N_NODES * NW];
static __device__ uint32_t g_radj[N_NODES * NW];
static __device__ uint32_t g_F[NW];
static __device__ uint32_t g_B[NW];
static __device__ int g_pivot;
static __device__ int g_i64flag;
static __device__ int g_bar[NBAR];

// ---------------------------------------------------------------------------
__global__ void init_kernel(const int* __restrict__ ei32) {
    int t = blockIdx.x * blockDim.x + threadIdx.x;   // 0..32767
    g_adj[t] = 0u;
    g_radj[t] = 0u;
    if (t < NBAR) g_bar[t] = 0;
    if (t == 0) {
        g_pivot = 0;
        // int64 little-endian with node ids < 1024 => every odd word is 0.
        int allzero = 1;
        for (int k = 0; k < 64; k++)
            if (ei32[2 * k + 1] != 0) { allzero = 0; break; }
        g_i64flag = allzero;
    }
}

// ---------------------------------------------------------------------------
// Pure-poll grid barrier. 64 blocks x 512 threads at 1 block/SM => all
// co-resident, spin deadlock-free.
__device__ __forceinline__ void grid_sync(int slot) {
    __syncthreads();
    if (threadIdx.x == 0) {
        __threadfence();
        atomicAdd(&g_bar[slot], 1);
        while (*(volatile int*)&g_bar[slot] < GRID) { }
        __threadfence();
    }
    __syncthreads();
}

// ---------------------------------------------------------------------------
__global__ void __launch_bounds__(TPB, 1)
fused_kernel(const int* __restrict__ ei32, const float* __restrict__ attr,
             float* __restrict__ out, int E) {
    __shared__ uint32_t sR[NW], sExp[NW], sFr[NW];
    __shared__ int sAny;

    const int tid  = blockIdx.x * TPB + threadIdx.x;   // 0..32767
    const int lane = threadIdx.x & 31;
    const int wid  = threadIdx.x >> 5;                 // 0..15
    const int row  = tid >> 5;                         // warp == row, 0..1023
    const int NN   = N_NODES * N_NODES;
    const int i64  = g_i64flag;

    // ---- P1: scatter adj/radj + pivot --------------------------------------
    {
        const int stride = GRID * TPB;                 // 32768
        const int nloops = (E + stride - 1) / stride;
        for (int i = 0; i < nloops; i++) {             // warp-uniform count
            int e = tid + i * stride;
            bool v = (e < E);
            int src = 0, dst = 0; float a = 1.0f;
            if (v) {
                if (i64) { src = ei32[2 * e]; dst = ei32[2 * (E + e)]; }
                else     { src = ei32[e];     dst = ei32[E + e]; }
                a = attr[e];
            }
            bool body = v && (a == 0.0f);
            if (body) {
                atomicOr(&g_adj[src * NW + (dst >> 5)], 1u << (dst & 31));
                atomicOr(&g_radj[dst * NW + (src >> 5)], 1u << (src & 31));
            }
            int m = __reduce_max_sync(FULLMASK, body ? dst : -1);
            if (lane == 0 && m >= 0) atomicMax(&g_pivot, m);
        }
    }
    grid_sync(0);

    // ---- P2: blocks 0,1 = BFS; blocks 2.. = copy original edges ------------
    if (blockIdx.x <= 1) {
        const uint32_t* Adj = (blockIdx.x == 0) ? g_adj : g_radj;
        const int p = *(volatile int*)&g_pivot;
        if (threadIdx.x < NW) { sR[threadIdx.x] = Adj[p * NW + threadIdx.x];
                                sExp[threadIdx.x] = 0u; }
        __syncthreads();
        for (int level = 0; level < N_NODES + 1; level++) {
            if (threadIdx.x == 0) sAny = 0;
            __syncthreads();
            if (threadIdx.x < NW) {
                sFr[threadIdx.x] = sR[threadIdx.x] & ~sExp[threadIdx.x];
                sExp[threadIdx.x] = sR[threadIdx.x];
                if (sFr[threadIdx.x]) sAny = 1;        // benign race
            }
            __syncthreads();
            if (!sAny) break;
            uint32_t accum = 0;
            #pragma unroll 1
            for (int ww = wid; ww < NW; ww += 16) {    // 16 warps, 2 words ea.
                uint32_t bits = sFr[ww];               // warp-uniform
                const uint32_t* pk = &Adj[(ww << 10) + lane];
                while (bits) {
                    int j0 = __ffs(bits) - 1; bits &= bits - 1;
                    int j1 = j0, j2 = j0, j3 = j0;
                    int j4 = j0, j5 = j0, j6 = j0, j7 = j0;
                    if (bits) { j1 = __ffs(bits) - 1; bits &= bits - 1; }
                    if (bits) { j2 = __ffs(bits) - 1; bits &= bits - 1; }
                    if (bits) { j3 = __ffs(bits) - 1; bits &= bits - 1; }
                    if (bits) { j4 = __ffs(bits) - 1; bits &= bits - 1; }
                    if (bits) { j5 = __ffs(bits) - 1; bits &= bits - 1; }
                    if (bits) { j6 = __ffs(bits) - 1; bits &= bits - 1; }
                    if (bits) { j7 = __ffs(bits) - 1; bits &= bits - 1; }
                    uint32_t v0 = pk[j0 << 5];
                    uint32_t v1 = pk[j1 << 5];
                    uint32_t v2 = pk[j2 << 5];
                    uint32_t v3 = pk[j3 << 5];
                    uint32_t v4 = pk[j4 << 5];
                    uint32_t v5 = pk[j5 << 5];
                    uint32_t v6 = pk[j6 << 5];
                    uint32_t v7 = pk[j7 << 5];
                    accum |= (v0 | v1) | (v2 | v3) | (v4 | v5) | (v6 | v7);
                }
            }
            if (accum) atomicOr(&sR[lane], accum);
            __syncthreads();
        }
        if (threadIdx.x < NW) {
            if (blockIdx.x == 0) g_F[threadIdx.x] = sR[threadIdx.x];
            else                 g_B[threadIdx.x] = sR[threadIdx.x];
        }
    } else {
        // Copy original edges (coalesced), overlapped with BFS.
        int t2 = (blockIdx.x - 2) * TPB + threadIdx.x;  // 0..31743
        for (int e = t2; e < E; e += (GRID - 2) * TPB) {
            int src, dst;
            if (i64) { src = ei32[2 * e]; dst = ei32[2 * (E + e)]; }
            else     { src = ei32[e];     dst = ei32[E + e]; }
            out[e] = (float)src;
            out[(E + NN) + e] = (float)dst;
            out[2 * (E + NN) + e] = attr[e];
        }
    }
    grid_sync(1);

    // ---- P3': closed-form closure + COALESCED full-row emit ----------------
    {
        const uint32_t Fl  = __ldcg(&g_F[lane]);       // lane-resident bitsets
        const uint32_t Bl  = __ldcg(&g_B[lane]);
        const uint32_t FBl = Fl & Bl;
        const int p = *(volatile int*)&g_pivot;
        const uint32_t pbit = (lane == (p >> 5)) ? (1u << (p & 31)) : 0u;

        const uint32_t adjrow = g_adj[(row << 5) + lane];
        const int inB = (__shfl_sync(FULLMASK, Bl, row >> 5) >> (row & 31)) & 1;

        uint32_t acc = adjrow;
        bool haveF = false;
        if (inB) { acc |= Fl | pbit; haveF = true; }   // closure(row) >= F u {p}
        uint32_t expanded = 0;

        #pragma unroll 1
        for (int round = 0; round < N_NODES; round++) {
            uint32_t delta = acc & ~expanded;
            if (!__any_sync(FULLMASK, delta != 0u)) break;
            expanded = acc;
            uint32_t add = 0;

            bool hitB = __any_sync(FULLMASK, (delta & Bl) != 0u);
            bool willF = haveF || hitB;
            if (hitB) add |= Fl | pbit;

            uint32_t loadbits = delta & ~FBl;          // F&B: closure=F, no load
            if (willF) loadbits &= ~Fl;                // F absorbed once F in acc

            uint32_t wordmask = __ballot_sync(FULLMASK, loadbits != 0u);
            while (wordmask) {
                int l = __ffs(wordmask) - 1; wordmask &= wordmask - 1;
                uint32_t bits = __shfl_sync(FULLMASK, loadbits, l);
                const uint32_t* pk = &g_adj[(l << 10) + lane];
                while (bits) {
                    int j0 = __ffs(bits) - 1; bits &= bits - 1;
                    int j1 = j0, j2 = j0, j3 = j0;
                    if (bits) { j1 = __ffs(bits) - 1; bits &= bits - 1; }
                    if (bits) { j2 = __ffs(bits) - 1; bits &= bits - 1; }
                    if (bits) { j3 = __ffs(bits) - 1; bits &= bits - 1; }
                    add |= pk[j0 << 5] | pk[j1 << 5] | pk[j2 << 5] | pk[j3 << 5];
                }
            }

            uint32_t na = acc | add;
            haveF = willF;
            if (__all_sync(FULLMASK, na == acc)) break;
            acc = na;
        }

        // sc for lane's word (row*32+lane); row output span is contiguous.
        uint32_t sc = acc & ~adjrow;
        const float fi = (float)row;
        float* so = out + E + (row << 10);                    // new_src row
        float* dd = out + (E + NN) + E + (row << 10);         // new_dst row
        float* ao = out + 2 * (E + NN) + E + (row << 10);     // new_attr row

        if ((E & 3) == 0) {
            // Coalesced: 8 iterations x 3 float4 stores; lane l covers floats
            // f = it*128 + l*4 + {0..3}; word = it*4 + (l>>3); bit = (l&7)*4+q.
            #pragma unroll
            for (int it = 0; it < 8; it++) {
                int w = (it << 2) + (lane >> 3);
                uint32_t nib = (__shfl_sync(FULLMASK, sc, w) >> ((lane & 7) << 2)) & 0xFu;
                int f = (it << 7) + (lane << 2);
                bool b0 = nib & 1u, b1 = (nib >> 1) & 1u;
                bool b2 = (nib >> 2) & 1u, b3 = (nib >> 3) & 1u;
                float4 s4 = make_float4(b0 ? fi : 0.f, b1 ? fi : 0.f,
                                        b2 ? fi : 0.f, b3 ? fi : 0.f);
                float4 d4 = make_float4(b0 ? (float)(f + 0) : 0.f,
                                        b1 ? (float)(f + 1) : 0.f,
                                        b2 ? (float)(f + 2) : 0.f,
                                        b3 ? (float)(f + 3) : 0.f);
                float4 a4 = make_float4(b0 ? 3.f : -1.f, b1 ? 3.f : -1.f,
                                        b2 ? 3.f : -1.f, b3 ? 3.f : -1.f);
                *(float4*)(so + f) = s4;
                *(float4*)(dd + f) = d4;
                *(float4*)(ao + f) = a4;
            }
        } else {
            // Scalar fallback (unaligned E). Still coalesced per instruction.
            #pragma unroll 1
            for (int it = 0; it < 32; it++) {
                int f = (it << 5) + lane;               // float index in row
                uint32_t scw = __shfl_sync(FULLMASK, sc, f >> 5);
                bool b = (scw >> (f & 31)) & 1u;
                so[f] = b ? fi : 0.f;
                dd[f] = b ? (float)f : 0.f;
                ao[f] = b ? 3.f : -1.f;
            }
        }
    }
}

// ---------------------------------------------------------------------------
extern "C" void kernel_launch(void* const* d_in, const int* in_sizes, int n_in,
                              void* d_out, int out_size) {
    const int* ei = (const int*)d_in[0];
    const float* attr = (const float*)d_in[1];
    float* out = (float*)d_out;
    int E = in_sizes[1];

    init_kernel<<<64, 512>>>(ei);
    fused_kernel<<<GRID, TPB>>>(ei, attr, out, E);
}